// round 15
// baseline (speedup 1.0000x reference)
#include <cuda_runtime.h>

#define W 512
#define H 512
#define NPLANE 48          // 16 batch * 3 channels
#define TX 128
#define TY 16
#define RAD 5
#define VC (TX + 2*RAD)    // 138 vertical-conv columns
#define PQ 139             // intermediate pitch in ulonglong2 units (odd)
#define NT 256             // 8 warps
#define TPX (W / TX)       // 4 tiles per row
#define TPY (H / TY)       // 32 tile rows
#define NBLOCKS (TPX * TPY * NPLANE)   // 6144 tiles
#define GRID 592           // 148 SMs x 4 CTAs: one persistent wave
#define NVT (VC * (TY/8))  // 276 vertical tasks

typedef unsigned long long u64;

__device__ double   g_accum;   // zero at module load; reset by last CTA each call
__device__ unsigned g_count;   // auto-wrapping completion counter

__device__ __forceinline__ u64 pack2(float a, float b) {
    u64 r; asm("mov.b64 %0, {%1,%2};" : "=l"(r) : "f"(a), "f"(b)); return r;
}
__device__ __forceinline__ void unpack2(u64 v, float& a, float& b) {
    asm("mov.b64 {%0,%1}, %2;" : "=f"(a), "=f"(b) : "l"(v));
}
__device__ __forceinline__ u64 fma2(u64 a, u64 b, u64 c) {
    u64 d; asm("fma.rn.f32x2 %0, %1, %2, %3;" : "=l"(d) : "l"(a), "l"(b), "l"(c)); return d;
}
__device__ __forceinline__ u64 mul2(u64 a, u64 b) {
    u64 d; asm("mul.rn.f32x2 %0, %1, %2;" : "=l"(d) : "l"(a), "l"(b)); return d;
}

// Register-resident taps (6 unique values; ptxas CSEs the packs).
#define GDEF constexpr float G[11] = { \
    0.00102838f, 0.00759874f, 0.03600078f, 0.10936071f, 0.21300553f, \
    0.26601174f, \
    0.21300553f, 0.10936071f, 0.03600078f, 0.00759874f, 0.00102838f }

// Vertical 11-tap, 8-output strip for one column, streaming 18 gmem rows.
// Channels: pair1 = (s, d) = (x+y, x-y);  pair2 = (s^2, d^2).
template <bool CHK>
__device__ __forceinline__ void vtask(const float* __restrict__ Xp,
                                      const float* __restrict__ Yp,
                                      int gx, int gyBase, bool colOK,
                                      ulonglong2* __restrict__ s_q,
                                      int c, int s) {
    GDEF;
    u64 a1[8], a2[8];
    #pragma unroll
    for (int o = 0; o < 8; ++o) { a1[o] = 0ull; a2[o] = 0ull; }

    #pragma unroll
    for (int j = 0; j < 18; ++j) {
        const int gy = gyBase + j;
        float xa = 0.f, ya = 0.f;
        if (!CHK || (colOK && (unsigned)gy < (unsigned)H)) {
            const int idx = gy * W + gx;
            xa = Xp[idx];
            ya = Yp[idx];
        }
        u64 v  = pack2(xa + ya, xa - ya);   // (s, d)
        u64 v2 = mul2(v, v);                // (s^2, d^2)
        #pragma unroll
        for (int o = 0; o < 8; ++o) {
            int k = j - o;
            if (k >= 0 && k < 11) {
                u64 gk = pack2(G[k], G[k]);
                a1[o] = fma2(v,  gk, a1[o]);
                a2[o] = fma2(v2, gk, a2[o]);
            }
        }
    }
    const int ryBase = s << 3;
    #pragma unroll
    for (int o = 0; o < 8; ++o)
        s_q[(ryBase + o) * PQ + c] = make_ulonglong2(a1[o], a2[o]);
}

__global__ __launch_bounds__(NT, 4) void ssim_main(const float* __restrict__ X,
                                                   const float* __restrict__ Y,
                                                   float* __restrict__ out) {
    extern __shared__ u64 sm[];
    ulonglong2* s_q = (ulonglong2*)sm;     // [TY][PQ]: (hs,hd),(hs2,hd2)
    // total: 16*139*16 = 35,584 B

    const int tid = threadIdx.x;
    float lsum = 0.f;

    // ---- Persistent tile loop: one wave of 592 CTAs covers all 6144 tiles ----
    for (int tile = blockIdx.x; tile < NBLOCKS; tile += GRID) {
        const int plane = tile >> 7;                  // / (TPX*TPY = 128)
        const int rem   = tile & 127;
        const int by    = rem >> 2;                   // / TPX
        const int bx    = rem & 3;

        const int x0 = bx * TX - RAD;
        const int y0 = by * TY - RAD;
        const float* Xp = X + (size_t)plane * (W * H);
        const float* Yp = Y + (size_t)plane * (W * H);
        const bool interior = (bx > 0) & (bx < TPX - 1) & (by > 0) & (by < TPY - 1);

        __syncthreads();   // previous tile's H reads complete before overwriting s_q

        // ---- Phase V: vertical conv straight from gmem ----
        // round 1: t = tid (s = t/138, c = t%138); round 2: 20 leftovers (s=1)
        if (interior) {
            if (tid < NVT - NT)
                vtask<false>(Xp, Yp, x0 + 118 + tid, y0 + 8, true, s_q, 118 + tid, 1);
            {
                int s = tid / VC;
                int c = tid - s * VC;
                vtask<false>(Xp, Yp, x0 + c, y0 + s * 8, true, s_q, c, s);
            }
        } else {
            if (tid < NVT - NT) {
                int c = 118 + tid;
                int gx = x0 + c;
                vtask<true>(Xp, Yp, gx, y0 + 8, (unsigned)gx < (unsigned)W, s_q, c, 1);
            }
            {
                int s = tid / VC;
                int c = tid - s * VC;
                int gx = x0 + c;
                vtask<true>(Xp, Yp, gx, y0 + s * 8, (unsigned)gx < (unsigned)W, s_q, c, s);
            }
        }
        __syncthreads();

        // ---- Phase H: horizontal conv + SSIM. 256 tasks = 16 rows x 16 strips ----
        {
            GDEF;
            const int r  = tid & 15;
            const int c0 = (tid >> 4) << 3;

            u64 a1[8], a2[8];
            #pragma unroll
            for (int o = 0; o < 8; ++o) { a1[o] = 0ull; a2[o] = 0ull; }

            #pragma unroll
            for (int j = 0; j < 18; ++j) {
                ulonglong2 vq = s_q[r * PQ + c0 + j];    // one LDS.128 per tap
                #pragma unroll
                for (int o = 0; o < 8; ++o) {
                    int k = j - o;
                    if (k >= 0 && k < 11) {
                        u64 gk = pack2(G[k], G[k]);
                        a1[o] = fma2(vq.x, gk, a1[o]);
                        a2[o] = fma2(vq.y, gk, a2[o]);
                    }
                }
            }

            // Packed epilogue: a1[o]=(ms,md); a2[o]=(P,Q). A=ms^2+md^2; B=ms^2-md^2.
            const u64 halfv  = pack2(0.5f, 0.5f);
            const u64 nhalfv = pack2(-0.5f, -0.5f);
            const u64 c1v    = pack2(1e-4f, 1e-4f);
            const u64 c2v    = pack2(9e-4f, 9e-4f);
            #pragma unroll
            for (int o = 0; o < 8; o += 2) {
                float ms2a, md2a, ms2b, md2b, Pa, Qa, Pb, Qb;
                unpack2(mul2(a1[o],     a1[o]),     ms2a, md2a);
                unpack2(mul2(a1[o + 1], a1[o + 1]), ms2b, md2b);
                unpack2(a2[o],     Pa, Qa);
                unpack2(a2[o + 1], Pb, Qb);
                u64 A  = pack2(ms2a + md2a, ms2b + md2b);
                u64 B  = pack2(ms2a - md2a, ms2b - md2b);
                u64 Ps = pack2(Pa + Qa, Pb + Qb);
                u64 Pd = pack2(Pa - Qa, Pb - Qb);
                u64 num1 = fma2(B, halfv, c1v);                      // 2*mu12 + c1
                u64 num2 = fma2(Pd, halfv, fma2(B, nhalfv, c2v));    // 2*sig12 + c2
                u64 den1 = fma2(A, halfv, c1v);                      // mu^2 sum + c1
                u64 den2 = fma2(Ps, halfv, fma2(A, nhalfv, c2v));    // sigsum + c2
                float n0, n1, d0, d1;
                unpack2(mul2(num1, num2), n0, n1);
                unpack2(mul2(den1, den2), d0, d1);
                lsum += __fdividef(n0, d0);
                lsum += __fdividef(n1, d1);
            }
        }
    }

    // ---- Final reduce -> one double atomic per CTA; last CTA finalizes ----
    #pragma unroll
    for (int off = 16; off; off >>= 1)
        lsum += __shfl_down_sync(0xffffffffu, lsum, off);
    __syncthreads();                       // last tile's smem reads done
    float* red = (float*)sm;
    if ((tid & 31) == 0) red[tid >> 5] = lsum;
    __syncthreads();
    if (tid == 0) {
        float bs = 0.f;
        #pragma unroll
        for (int i = 0; i < NT / 32; ++i) bs += red[i];
        atomicAdd(&g_accum, (double)bs);
        __threadfence();
        unsigned prev = atomicInc(&g_count, GRID - 1);     // wraps to 0 on last
        if (prev == GRID - 1) {
            double total = atomicAdd(&g_accum, 0.0);       // ordered read
            out[0] = (float)(total * (1.0 / ((double)NPLANE * W * H)));
            g_accum = 0.0;                                 // ready for next replay
        }
    }
}

extern "C" void kernel_launch(void* const* d_in, const int* in_sizes, int n_in,
                              void* d_out, int out_size) {
    const float* X = (const float*)d_in[0];
    const float* Y = (const float*)d_in[1];
    // d_in[2] (window) unused: taps fixed by problem definition, baked as constants.

    const int smem = TY * PQ * 16;   // 35,584 B
    static int configured = 0;
    if (!configured) {
        cudaFuncSetAttribute(ssim_main, cudaFuncAttributeMaxDynamicSharedMemorySize, smem);
        configured = 1;
    }

    ssim_main<<<GRID, NT, smem>>>(X, Y, (float*)d_out);
}

// round 16
// speedup vs baseline: 1.1328x; 1.1328x over previous
#include <cuda_runtime.h>

#define W 512
#define H 512
#define NPLANE 48          // 16 batch * 3 channels
#define TX 256
#define TY 8
#define RAD 5
#define VC (TX + 2*RAD)    // 266 vertical-conv columns
#define PQ 267             // intermediate pitch in ulonglong2 units (odd)
#define NT 256             // 8 warps
#define TPX (W / TX)       // 2
#define TPY (H / TY)       // 64
#define NBLOCKS (TPX * TPY * NPLANE)   // 6144
#define NVT VC             // 266 vertical tasks (one strip)

typedef unsigned long long u64;

__device__ double   g_accum;   // zero at module load; reset by last CTA each call
__device__ unsigned g_count;   // auto-wrapping completion counter

__device__ __forceinline__ u64 pack2(float a, float b) {
    u64 r; asm("mov.b64 %0, {%1,%2};" : "=l"(r) : "f"(a), "f"(b)); return r;
}
__device__ __forceinline__ void unpack2(u64 v, float& a, float& b) {
    asm("mov.b64 {%0,%1}, %2;" : "=f"(a), "=f"(b) : "l"(v));
}
__device__ __forceinline__ u64 fma2(u64 a, u64 b, u64 c) {
    u64 d; asm("fma.rn.f32x2 %0, %1, %2, %3;" : "=l"(d) : "l"(a), "l"(b), "l"(c)); return d;
}
__device__ __forceinline__ u64 mul2(u64 a, u64 b) {
    u64 d; asm("mul.rn.f32x2 %0, %1, %2;" : "=l"(d) : "l"(a), "l"(b)); return d;
}

// Register-resident taps (6 unique values; ptxas CSEs the packs).
#define GDEF constexpr float G[11] = { \
    0.00102838f, 0.00759874f, 0.03600078f, 0.10936071f, 0.21300553f, \
    0.26601174f, \
    0.21300553f, 0.10936071f, 0.03600078f, 0.00759874f, 0.00102838f }

// Vertical 11-tap, 8-output strip for one column, streaming 18 gmem rows.
// Channels: pair1 = (s, d) = (x+y, x-y);  pair2 = (s^2, d^2).
// CHKY: per-row y-bounds check (only y-edge tiles). colOK: uniform per task.
template <bool CHKY>
__device__ __forceinline__ void vtask(const float* __restrict__ Xp,
                                      const float* __restrict__ Yp,
                                      int gx, int gyBase, bool colOK,
                                      ulonglong2* __restrict__ s_q, int c) {
    if (!colOK) {                       // whole column out of range: zeros, no loads
        #pragma unroll
        for (int o = 0; o < 8; ++o)
            s_q[o * PQ + c] = make_ulonglong2(0ull, 0ull);
        return;
    }
    GDEF;
    u64 a1[8], a2[8];
    #pragma unroll
    for (int o = 0; o < 8; ++o) { a1[o] = 0ull; a2[o] = 0ull; }

    #pragma unroll
    for (int j = 0; j < 18; ++j) {
        const int gy = gyBase + j;
        float xa = 0.f, ya = 0.f;
        if (!CHKY || (unsigned)gy < (unsigned)H) {
            const int idx = gy * W + gx;
            xa = Xp[idx];
            ya = Yp[idx];
        }
        u64 v  = pack2(xa + ya, xa - ya);   // (s, d)
        u64 v2 = mul2(v, v);                // (s^2, d^2)
        #pragma unroll
        for (int o = 0; o < 8; ++o) {
            int k = j - o;
            if (k >= 0 && k < 11) {
                u64 gk = pack2(G[k], G[k]);
                a1[o] = fma2(v,  gk, a1[o]);
                a2[o] = fma2(v2, gk, a2[o]);
            }
        }
    }
    #pragma unroll
    for (int o = 0; o < 8; ++o)
        s_q[o * PQ + c] = make_ulonglong2(a1[o], a2[o]);
}

__global__ __launch_bounds__(NT, 4) void ssim_main(const float* __restrict__ X,
                                                   const float* __restrict__ Y,
                                                   float* __restrict__ out) {
    extern __shared__ u64 sm[];
    ulonglong2* s_q = (ulonglong2*)sm;     // [TY][PQ]: (hs,hd),(hs2,hd2)
    // total: 8*267*16 = 34,176 B

    const int tid = threadIdx.x;
    const int x0 = blockIdx.x * TX - RAD;  // leftmost v-column (gx)
    const int y0 = blockIdx.y * TY - RAD;  // topmost input row
    const float* Xp = X + (size_t)blockIdx.z * (W * H);
    const float* Yp = Y + (size_t)blockIdx.z * (W * H);

    const bool yIn = (blockIdx.y > 0) & (blockIdx.y < TPY - 1);  // 62/64 tiles

    // ---- Phase V: vertical conv straight from gmem ----
    // 266 tasks: leftover (c = 256+tid, tid<10) first, then main (c = tid).
    if (yIn) {
        if (tid < NVT - NT) {
            int c = NT + tid, gx = x0 + c;
            vtask<false>(Xp, Yp, gx, y0, (unsigned)gx < (unsigned)W, s_q, c);
        }
        {
            int gx = x0 + tid;
            vtask<false>(Xp, Yp, gx, y0, (unsigned)gx < (unsigned)W, s_q, tid);
        }
    } else {
        if (tid < NVT - NT) {
            int c = NT + tid, gx = x0 + c;
            vtask<true>(Xp, Yp, gx, y0, (unsigned)gx < (unsigned)W, s_q, c);
        }
        {
            int gx = x0 + tid;
            vtask<true>(Xp, Yp, gx, y0, (unsigned)gx < (unsigned)W, s_q, tid);
        }
    }
    __syncthreads();

    // ---- Phase H: horizontal conv + SSIM. 256 tasks = 8 rows x 32 strips ----
    // r = tid & 7, c0 = (tid >> 3) * 8. Conflict-free (pitch 12 words mod 32).
    float lsum = 0.f;
    {
        GDEF;
        const int r  = tid & 7;
        const int c0 = (tid >> 3) << 3;

        u64 a1[8], a2[8];
        #pragma unroll
        for (int o = 0; o < 8; ++o) { a1[o] = 0ull; a2[o] = 0ull; }

        #pragma unroll
        for (int j = 0; j < 18; ++j) {
            ulonglong2 vq = s_q[r * PQ + c0 + j];    // one LDS.128 per tap
            #pragma unroll
            for (int o = 0; o < 8; ++o) {
                int k = j - o;
                if (k >= 0 && k < 11) {
                    u64 gk = pack2(G[k], G[k]);
                    a1[o] = fma2(vq.x, gk, a1[o]);
                    a2[o] = fma2(vq.y, gk, a2[o]);
                }
            }
        }

        // Packed epilogue: a1[o]=(ms,md); a2[o]=(P,Q). A=ms^2+md^2; B=ms^2-md^2.
        const u64 halfv  = pack2(0.5f, 0.5f);
        const u64 nhalfv = pack2(-0.5f, -0.5f);
        const u64 c1v    = pack2(1e-4f, 1e-4f);
        const u64 c2v    = pack2(9e-4f, 9e-4f);
        #pragma unroll
        for (int o = 0; o < 8; o += 2) {
            float ms2a, md2a, ms2b, md2b, Pa, Qa, Pb, Qb;
            unpack2(mul2(a1[o],     a1[o]),     ms2a, md2a);
            unpack2(mul2(a1[o + 1], a1[o + 1]), ms2b, md2b);
            unpack2(a2[o],     Pa, Qa);
            unpack2(a2[o + 1], Pb, Qb);
            u64 A  = pack2(ms2a + md2a, ms2b + md2b);
            u64 B  = pack2(ms2a - md2a, ms2b - md2b);
            u64 Ps = pack2(Pa + Qa, Pb + Qb);
            u64 Pd = pack2(Pa - Qa, Pb - Qb);
            u64 num1 = fma2(B, halfv, c1v);                      // 2*mu12 + c1
            u64 num2 = fma2(Pd, halfv, fma2(B, nhalfv, c2v));    // 2*sig12 + c2
            u64 den1 = fma2(A, halfv, c1v);                      // mu^2 sum + c1
            u64 den2 = fma2(Ps, halfv, fma2(A, nhalfv, c2v));    // sigsum + c2
            float n0, n1, d0, d1;
            unpack2(mul2(num1, num2), n0, n1);
            unpack2(mul2(den1, den2), d0, d1);
            lsum += __fdividef(n0, d0);
            lsum += __fdividef(n1, d1);
        }
    }

    // ---- Reduce -> double atomic; last CTA finalizes ----
    #pragma unroll
    for (int off = 16; off; off >>= 1)
        lsum += __shfl_down_sync(0xffffffffu, lsum, off);
    __syncthreads();                       // smem reads done; reuse for reduce
    float* red = (float*)sm;
    if ((tid & 31) == 0) red[tid >> 5] = lsum;
    __syncthreads();
    if (tid == 0) {
        float bs = 0.f;
        #pragma unroll
        for (int i = 0; i < NT / 32; ++i) bs += red[i];
        atomicAdd(&g_accum, (double)bs);
        __threadfence();
        unsigned prev = atomicInc(&g_count, NBLOCKS - 1);  // wraps to 0 on last
        if (prev == NBLOCKS - 1) {
            double total = atomicAdd(&g_accum, 0.0);       // ordered read
            out[0] = (float)(total * (1.0 / ((double)NPLANE * W * H)));
            g_accum = 0.0;                                 // ready for next replay
        }
    }
}

extern "C" void kernel_launch(void* const* d_in, const int* in_sizes, int n_in,
                              void* d_out, int out_size) {
    const float* X = (const float*)d_in[0];
    const float* Y = (const float*)d_in[1];
    // d_in[2] (window) unused: taps fixed by problem definition, baked as constants.

    const int smem = TY * PQ * 16;   // 34,176 B
    static int configured = 0;
    if (!configured) {
        cudaFuncSetAttribute(ssim_main, cudaFuncAttributeMaxDynamicSharedMemorySize, smem);
        configured = 1;
    }

    dim3 grid(TPX, TPY, NPLANE);
    ssim_main<<<grid, NT, smem>>>(X, Y, (float*)d_out);
}

// round 17
// speedup vs baseline: 1.2174x; 1.0747x over previous
#include <cuda_runtime.h>

#define W 512
#define H 512
#define NPLANE 48          // 16 batch * 3 channels
#define TX 512             // full image row per tile
#define TY 8
#define RAD 5
#define VC (TX + 2*RAD)    // 522 intermediate columns (10 are out-of-image)
#define PQ 523             // intermediate pitch in ulonglong2 units (odd)
#define NT 512             // 16 warps
#define TPY (H / TY)       // 64
#define NBLOCKS (TPY * NPLANE)   // 3072
typedef unsigned long long u64;

__device__ double   g_accum;   // zero at module load; reset by last CTA each call
__device__ unsigned g_count;   // auto-wrapping completion counter

__device__ __forceinline__ u64 pack2(float a, float b) {
    u64 r; asm("mov.b64 %0, {%1,%2};" : "=l"(r) : "f"(a), "f"(b)); return r;
}
__device__ __forceinline__ void unpack2(u64 v, float& a, float& b) {
    asm("mov.b64 {%0,%1}, %2;" : "=f"(a), "=f"(b) : "l"(v));
}
__device__ __forceinline__ u64 fma2(u64 a, u64 b, u64 c) {
    u64 d; asm("fma.rn.f32x2 %0, %1, %2, %3;" : "=l"(d) : "l"(a), "l"(b), "l"(c)); return d;
}
__device__ __forceinline__ u64 mul2(u64 a, u64 b) {
    u64 d; asm("mul.rn.f32x2 %0, %1, %2;" : "=l"(d) : "l"(a), "l"(b)); return d;
}

// Register-resident taps (6 unique values; ptxas CSEs the packs).
#define GDEF constexpr float G[11] = { \
    0.00102838f, 0.00759874f, 0.03600078f, 0.10936071f, 0.21300553f, \
    0.26601174f, \
    0.21300553f, 0.10936071f, 0.03600078f, 0.00759874f, 0.00102838f }

// Vertical 11-tap, 8-output strip for one column, streaming 18 gmem rows.
// Channels: pair1 = (s, d) = (x+y, x-y);  pair2 = (s^2, d^2).
// CHKY: per-row y-bounds check (only the 2 y-edge tile rows compile this in).
template <bool CHKY>
__device__ __forceinline__ void vtask(const float* __restrict__ Xp,
                                      const float* __restrict__ Yp,
                                      int gx, int gyBase,
                                      ulonglong2* __restrict__ s_q, int c) {
    GDEF;
    u64 a1[8], a2[8];
    #pragma unroll
    for (int o = 0; o < 8; ++o) { a1[o] = 0ull; a2[o] = 0ull; }

    #pragma unroll
    for (int j = 0; j < 18; ++j) {
        const int gy = gyBase + j;
        float xa = 0.f, ya = 0.f;
        if (!CHKY || (unsigned)gy < (unsigned)H) {
            const int idx = gy * W + gx;
            xa = Xp[idx];
            ya = Yp[idx];
        }
        u64 v  = pack2(xa + ya, xa - ya);   // (s, d)
        u64 v2 = mul2(v, v);                // (s^2, d^2)
        #pragma unroll
        for (int o = 0; o < 8; ++o) {
            int k = j - o;
            if (k >= 0 && k < 11) {
                u64 gk = pack2(G[k], G[k]);
                a1[o] = fma2(v,  gk, a1[o]);
                a2[o] = fma2(v2, gk, a2[o]);
            }
        }
    }
    #pragma unroll
    for (int o = 0; o < 8; ++o)
        s_q[o * PQ + c] = make_ulonglong2(a1[o], a2[o]);
}

__global__ __launch_bounds__(NT, 2) void ssim_main(const float* __restrict__ X,
                                                   const float* __restrict__ Y,
                                                   float* __restrict__ out) {
    extern __shared__ u64 sm[];
    ulonglong2* s_q = (ulonglong2*)sm;     // [TY][PQ]: (hs,hd),(hs2,hd2)
    // total: 8*523*16 = 66,944 B

    const int tid = threadIdx.x;
    const int by  = blockIdx.x;            // tile row 0..63
    const int y0  = by * TY - RAD;         // topmost input row
    const float* Xp = X + (size_t)blockIdx.y * (W * H);
    const float* Yp = Y + (size_t)blockIdx.y * (W * H);

    // ---- Phase V ----
    // The 10 out-of-image halo columns (c<5 or c>=517) are pure zero-stores.
    if (tid < 10) {
        const int c = (tid < 5) ? tid : (TX + RAD + tid - 5);   // 0..4, 517..521
        #pragma unroll
        for (int o = 0; o < 8; ++o)
            s_q[o * PQ + c] = make_ulonglong2(0ull, 0ull);
    }
    // Main round: 512 real columns on 512 threads, gx = tid (coalesced),
    // no x-bounds checks anywhere.
    if ((by > 0) & (by < TPY - 1)) {
        vtask<false>(Xp, Yp, tid, y0, s_q, tid + RAD);
    } else {
        vtask<true>(Xp, Yp, tid, y0, s_q, tid + RAD);
    }
    __syncthreads();

    // ---- Phase H: horizontal conv + SSIM. 512 tasks = 8 rows x 64 strips ----
    // r = tid & 7, c0 = (tid >> 3) * 8. Conflict-free (pitch = 12 words mod 32).
    float lsum = 0.f;
    {
        GDEF;
        const int r  = tid & 7;
        const int c0 = (tid >> 3) << 3;

        u64 a1[8], a2[8];
        #pragma unroll
        for (int o = 0; o < 8; ++o) { a1[o] = 0ull; a2[o] = 0ull; }

        #pragma unroll
        for (int j = 0; j < 18; ++j) {
            ulonglong2 vq = s_q[r * PQ + c0 + j];    // one LDS.128 per tap
            #pragma unroll
            for (int o = 0; o < 8; ++o) {
                int k = j - o;
                if (k >= 0 && k < 11) {
                    u64 gk = pack2(G[k], G[k]);
                    a1[o] = fma2(vq.x, gk, a1[o]);
                    a2[o] = fma2(vq.y, gk, a2[o]);
                }
            }
        }

        // Packed epilogue: a1[o]=(ms,md); a2[o]=(P,Q). A=ms^2+md^2; B=ms^2-md^2.
        const u64 halfv  = pack2(0.5f, 0.5f);
        const u64 nhalfv = pack2(-0.5f, -0.5f);
        const u64 c1v    = pack2(1e-4f, 1e-4f);
        const u64 c2v    = pack2(9e-4f, 9e-4f);
        #pragma unroll
        for (int o = 0; o < 8; o += 2) {
            float ms2a, md2a, ms2b, md2b, Pa, Qa, Pb, Qb;
            unpack2(mul2(a1[o],     a1[o]),     ms2a, md2a);
            unpack2(mul2(a1[o + 1], a1[o + 1]), ms2b, md2b);
            unpack2(a2[o],     Pa, Qa);
            unpack2(a2[o + 1], Pb, Qb);
            u64 A  = pack2(ms2a + md2a, ms2b + md2b);
            u64 B  = pack2(ms2a - md2a, ms2b - md2b);
            u64 Ps = pack2(Pa + Qa, Pb + Qb);
            u64 Pd = pack2(Pa - Qa, Pb - Qb);
            u64 num1 = fma2(B, halfv, c1v);                      // 2*mu12 + c1
            u64 num2 = fma2(Pd, halfv, fma2(B, nhalfv, c2v));    // 2*sig12 + c2
            u64 den1 = fma2(A, halfv, c1v);                      // mu^2 sum + c1
            u64 den2 = fma2(Ps, halfv, fma2(A, nhalfv, c2v));    // sigsum + c2
            float n0, n1, d0, d1;
            unpack2(mul2(num1, num2), n0, n1);
            unpack2(mul2(den1, den2), d0, d1);
            lsum += __fdividef(n0, d0);
            lsum += __fdividef(n1, d1);
        }
    }

    // ---- Reduce -> double atomic; last CTA finalizes ----
    #pragma unroll
    for (int off = 16; off; off >>= 1)
        lsum += __shfl_down_sync(0xffffffffu, lsum, off);
    __syncthreads();                       // smem reads done; reuse for reduce
    float* red = (float*)sm;
    if ((tid & 31) == 0) red[tid >> 5] = lsum;
    __syncthreads();
    if (tid == 0) {
        float bs = 0.f;
        #pragma unroll
        for (int i = 0; i < NT / 32; ++i) bs += red[i];
        atomicAdd(&g_accum, (double)bs);
        __threadfence();
        unsigned prev = atomicInc(&g_count, NBLOCKS - 1);  // wraps to 0 on last
        if (prev == NBLOCKS - 1) {
            double total = atomicAdd(&g_accum, 0.0);       // ordered read
            out[0] = (float)(total * (1.0 / ((double)NPLANE * W * H)));
            g_accum = 0.0;                                 // ready for next replay
        }
    }
}

extern "C" void kernel_launch(void* const* d_in, const int* in_sizes, int n_in,
                              void* d_out, int out_size) {
    const float* X = (const float*)d_in[0];
    const float* Y = (const float*)d_in[1];
    // d_in[2] (window) unused: taps fixed by problem definition, baked as constants.

    const int smem = TY * PQ * 16;   // 66,944 B
    static int configured = 0;
    if (!configured) {
        cudaFuncSetAttribute(ssim_main, cudaFuncAttributeMaxDynamicSharedMemorySize, smem);
        configured = 1;
    }

    dim3 grid(TPY, NPLANE);
    ssim_main<<<grid, NT, smem>>>(X, Y, (float*)d_out);
}